// round 13
// baseline (speedup 1.0000x reference)
#include <cuda_runtime.h>
#include <cuda_fp16.h>
#include <cstdint>
#include <math.h>

#define DHID 128
#define MAX_ENTS 100000
#define MAX_RELS 1000
#define MAX_EDGES 2000000
#define RRELU_SLOPE 0.22916666666666666f
#define PAD 132

typedef uint32_t u32;

__device__ __half2 g_hWh[MAX_ENTS * 64];         // h@Wn fp16
__device__ __half2 g_relWh[MAX_RELS * 64];       // rel@Wn fp16
__device__ int     g_cnt[MAX_ENTS];              // per-dst edge counts
__device__ int     g_off[MAX_ENTS];              // bucket start offsets
__device__ int     g_cur[MAX_ENTS];              // scatter cursors
__device__ int     g_bsum[256];                  // scan partials
__device__ uint2   g_rec[MAX_EDGES];             // (src | et<<17, norm_bits)

__device__ __forceinline__ u32 f2tf(float x) {
    u32 r; asm("cvt.rna.tf32.f32 %0, %1;" : "=r"(r) : "f"(x)); return r;
}
__device__ __forceinline__ void mma8(float* c, u32 a0, u32 a1, u32 a2, u32 a3,
                                     u32 b0, u32 b1) {
    asm volatile(
        "mma.sync.aligned.m16n8k8.row.col.f32.tf32.tf32.f32 "
        "{%0,%1,%2,%3}, {%4,%5,%6,%7}, {%8,%9}, {%0,%1,%2,%3};"
        : "+f"(c[0]), "+f"(c[1]), "+f"(c[2]), "+f"(c[3])
        : "r"(a0), "r"(a1), "r"(a2), "r"(a3), "r"(b0), "r"(b1));
}
__device__ __forceinline__ void add8(float4& acc0, float4& acc1,
                                     uint4 a, uint4 b, float n) {
    float2 p, q;
    p = __half22float2(*(__half2*)&a.x); q = __half22float2(*(__half2*)&b.x);
    acc0.x += (p.x + q.x) * n; acc0.y += (p.y + q.y) * n;
    p = __half22float2(*(__half2*)&a.y); q = __half22float2(*(__half2*)&b.y);
    acc0.z += (p.x + q.x) * n; acc0.w += (p.y + q.y) * n;
    p = __half22float2(*(__half2*)&a.z); q = __half22float2(*(__half2*)&b.z);
    acc1.x += (p.x + q.x) * n; acc1.y += (p.y + q.y) * n;
    p = __half22float2(*(__half2*)&a.w); q = __half22float2(*(__half2*)&b.w);
    acc1.z += (p.x + q.x) * n; acc1.w += (p.y + q.y) * n;
}

// ---------------------------------------------------------------------------
// Edge counting sort by dst (side stream, overlapped with gemm16)
// ---------------------------------------------------------------------------
extern "C" __global__ void k_zero(int* __restrict__ p, int n) {
    int i = blockIdx.x * 1024 + threadIdx.x;
    if (i < n) p[i] = 0;
}

extern "C" __global__ void __launch_bounds__(256)
k_hist(const int* __restrict__ dst, int E)
{
    int e = blockIdx.x * 256 + threadIdx.x;
    if (e < E) atomicAdd(&g_cnt[dst[e]], 1);
}

extern "C" __global__ void __launch_bounds__(1024)
k_scan1(int N)
{
    __shared__ int smi[1024];
    int i = blockIdx.x * 1024 + threadIdx.x;
    int v = (i < N) ? g_cnt[i] : 0;
    smi[threadIdx.x] = v;
    __syncthreads();
    for (int off = 512; off > 0; off >>= 1) {
        if (threadIdx.x < off) smi[threadIdx.x] += smi[threadIdx.x + off];
        __syncthreads();
    }
    if (threadIdx.x == 0) g_bsum[blockIdx.x] = smi[0];
}

extern "C" __global__ void __launch_bounds__(256)
k_scan2(int nb)
{
    __shared__ int s[256];
    int t = threadIdx.x;
    int v = (t < nb) ? g_bsum[t] : 0;
    s[t] = v;
    __syncthreads();
    #pragma unroll
    for (int off = 1; off < 256; off <<= 1) {
        int x = (t >= off) ? s[t - off] : 0;
        __syncthreads();
        s[t] += x;
        __syncthreads();
    }
    if (t < nb) g_bsum[t] = s[t] - v;   // exclusive
}

extern "C" __global__ void __launch_bounds__(1024)
k_scan3(int N)
{
    __shared__ int smi[1024];
    int i = blockIdx.x * 1024 + threadIdx.x;
    int v = (i < N) ? g_cnt[i] : 0;
    smi[threadIdx.x] = v;
    __syncthreads();
    #pragma unroll
    for (int off = 1; off < 1024; off <<= 1) {
        int x = (threadIdx.x >= off) ? smi[threadIdx.x - off] : 0;
        __syncthreads();
        smi[threadIdx.x] += x;
        __syncthreads();
    }
    if (i < N) {
        int ex = smi[threadIdx.x] - v + g_bsum[blockIdx.x];
        g_off[i] = ex;
        g_cur[i] = ex;
    }
}

extern "C" __global__ void __launch_bounds__(256)
k_scatter(const int* __restrict__ src, const int* __restrict__ dst,
          const int* __restrict__ et, const float* __restrict__ enorm, int E)
{
    int e = blockIdx.x * 256 + threadIdx.x;
    if (e >= E) return;
    int d   = dst[e];
    int pos = atomicAdd(&g_cur[d], 1);
    g_rec[pos] = make_uint2((u32)src[e] | ((u32)et[e] << 17),
                            __float_as_uint(enorm[e]));
}

// ---------------------------------------------------------------------------
// k_gemm16: fp16 out = normalize(ent) @ Wn rows [0,N); rel rows [N,N+R).
// Persistent, 2 CTA/SM. smem: WT[128][PAD] | hs[64][PAD] tf32.
// ---------------------------------------------------------------------------
extern "C" __global__ void __launch_bounds__(512, 2)
k_gemm16(const float* __restrict__ ent, const float* __restrict__ rel,
         const float* __restrict__ W, int N, int R, int numTiles)
{
    extern __shared__ u32 smu[];
    u32* WT = smu;               // [n][k] tf32
    u32* hs = smu + 128 * PAD;   // [row][k] tf32
    const int tid  = threadIdx.x;
    const int lane = tid & 31;
    const int w    = tid >> 5;
    const int gid  = lane >> 2;
    const int t4   = lane & 3;

    for (int idx = tid; idx < 128 * 128; idx += 512) {
        int k = idx >> 7, n = idx & 127;
        WT[n * PAD + k] = f2tf(W[idx]);
    }
    __syncthreads();

    const int rb = (w >> 2) * 16;
    const int cb = (w & 3) * 32;

    for (int tile = blockIdx.x; tile < numTiles; tile += gridDim.x) {
        const int base = tile * 64;

        #pragma unroll
        for (int rr = 0; rr < 4; rr++) {
            int row = w * 4 + rr, node = base + row;
            uint4 o = make_uint4(0u, 0u, 0u, 0u);
            if (node < N) {
                float4 v = *(const float4*)(ent + (size_t)node * 128 + lane * 4);
                float ss = v.x * v.x + v.y * v.y + v.z * v.z + v.w * v.w;
                #pragma unroll
                for (int off = 16; off > 0; off >>= 1)
                    ss += __shfl_xor_sync(0xffffffffu, ss, off);
                float rn = 1.0f / fmaxf(sqrtf(ss), 1e-12f);
                o = make_uint4(f2tf(v.x * rn), f2tf(v.y * rn),
                               f2tf(v.z * rn), f2tf(v.w * rn));
            } else if (node < N + R) {
                float4 v = *(const float4*)(rel + (size_t)(node - N) * 128 + lane * 4);
                o = make_uint4(f2tf(v.x), f2tf(v.y), f2tf(v.z), f2tf(v.w));
            }
            *(uint4*)(hs + row * PAD + lane * 4) = o;
        }
        __syncthreads();

        float acc[4][4];
        #pragma unroll
        for (int nt = 0; nt < 4; nt++)
            #pragma unroll
            for (int i = 0; i < 4; i++) acc[nt][i] = 0.f;

        #pragma unroll
        for (int s = 0; s < 16; s++) {
            const int kb = s * 8;
            u32 a0 = hs[(rb + gid) * PAD + kb + t4];
            u32 a1 = hs[(rb + 8 + gid) * PAD + kb + t4];
            u32 a2 = hs[(rb + gid) * PAD + kb + t4 + 4];
            u32 a3 = hs[(rb + 8 + gid) * PAD + kb + t4 + 4];
            #pragma unroll
            for (int nt = 0; nt < 4; nt++) {
                int c0 = cb + nt * 8 + gid;
                u32 b0 = WT[c0 * PAD + kb + t4];
                u32 b1 = WT[c0 * PAD + kb + t4 + 4];
                mma8(acc[nt], a0, a1, a2, a3, b0, b1);
            }
        }

        #pragma unroll
        for (int nt = 0; nt < 4; nt++) {
            int rl = rb + gid;
            int c  = cb + nt * 8 + 2 * t4;
            #pragma unroll
            for (int half = 0; half < 2; half++) {
                int node = base + rl + half * 8;
                __half2 p = __floats2half2_rn(acc[nt][half * 2], acc[nt][half * 2 + 1]);
                if (node < N)          g_hWh[(size_t)node * 64 + (c >> 1)] = p;
                else if (node < N + R) g_relWh[(size_t)(node - N) * 64 + (c >> 1)] = p;
            }
        }
        __syncthreads();
    }
}

// ---------------------------------------------------------------------------
// k_agg2: HALF-WARP per dst (16 lanes x uint4 = 256B row), no smem.
// acc = 0 + sum (hW[src]+relW[et])*norm; writes message sums into x.
// ---------------------------------------------------------------------------
extern "C" __global__ void __launch_bounds__(256)
k_agg2(float* __restrict__ x, int N)
{
    int d = blockIdx.x * 16 + (threadIdx.x >> 4);
    if (d >= N) return;
    int l = threadIdx.x & 15;

    const uint4* hW4  = (const uint4*)g_hWh;     // 16 uint4 per row
    const uint4* rlW4 = (const uint4*)g_relWh;

    float4 acc0 = make_float4(0.f, 0.f, 0.f, 0.f);
    float4 acc1 = make_float4(0.f, 0.f, 0.f, 0.f);
    const int s0  = g_off[d];
    const int cnt = g_cnt[d];

    int i = 0;
    for (; i + 4 <= cnt; i += 4) {
        uint2 r0 = __ldg(&g_rec[s0 + i]);
        uint2 r1 = __ldg(&g_rec[s0 + i + 1]);
        uint2 r2 = __ldg(&g_rec[s0 + i + 2]);
        uint2 r3 = __ldg(&g_rec[s0 + i + 3]);
        uint4 a0 = __ldg(&hW4[(size_t)(r0.x & 0x1FFFF) * 16 + l]);
        uint4 a1 = __ldg(&hW4[(size_t)(r1.x & 0x1FFFF) * 16 + l]);
        uint4 a2 = __ldg(&hW4[(size_t)(r2.x & 0x1FFFF) * 16 + l]);
        uint4 a3 = __ldg(&hW4[(size_t)(r3.x & 0x1FFFF) * 16 + l]);
        uint4 b0 = __ldg(&rlW4[(size_t)(r0.x >> 17) * 16 + l]);
        uint4 b1 = __ldg(&rlW4[(size_t)(r1.x >> 17) * 16 + l]);
        uint4 b2 = __ldg(&rlW4[(size_t)(r2.x >> 17) * 16 + l]);
        uint4 b3 = __ldg(&rlW4[(size_t)(r3.x >> 17) * 16 + l]);
        add8(acc0, acc1, a0, b0, __uint_as_float(r0.y));
        add8(acc0, acc1, a1, b1, __uint_as_float(r1.y));
        add8(acc0, acc1, a2, b2, __uint_as_float(r2.y));
        add8(acc0, acc1, a3, b3, __uint_as_float(r3.y));
    }
    for (; i < cnt; i++) {
        uint2 r = __ldg(&g_rec[s0 + i]);
        uint4 a = __ldg(&hW4[(size_t)(r.x & 0x1FFFF) * 16 + l]);
        uint4 b = __ldg(&rlW4[(size_t)(r.x >> 17) * 16 + l]);
        add8(acc0, acc1, a, b, __uint_as_float(r.y));
    }

    *(float4*)(x + (size_t)d * 128 + l * 8)     = acc0;
    *(float4*)(x + (size_t)d * 128 + l * 8 + 4) = acc1;
}

// ---------------------------------------------------------------------------
// k_finalX: fused self-loop + gate.
// x holds message sums (agg). Per 64-row tile:
//   hsA = normalize(ent)     (tf32)
//   MMA1: acc = h @ Ws^T;  h_cur = rrelu(acc + agg);  hs2 = h_cur
//   MMA2: logits = h_cur @ Wt^T;  gate = sigmoid(logits + b)
//   x = gate*h_cur + (1-gate)*his
// Persistent, 1 CTA/SM (202.8 KB smem), 512 threads.
// ---------------------------------------------------------------------------
extern "C" __global__ void __launch_bounds__(512, 1)
k_finalX(float* __restrict__ x,
         const float* __restrict__ ent,
         const float* __restrict__ Ws,
         const float* __restrict__ Wt,
         const float* __restrict__ bias,
         const float* __restrict__ his,
         int N, int numTiles)
{
    extern __shared__ float sm[];
    u32*   WTs = (u32*)sm;                    // Ws^T [n][k] tf32
    u32*   WTt = (u32*)sm + 128 * PAD;        // Wt^T [n][k] tf32
    u32*   hsA = (u32*)sm + 2 * 128 * PAD;    // normalized h tile [64][PAD] tf32
    float* hs2 = sm + 2 * 128 * PAD + 64 * PAD; // agg -> h_cur tile [64][PAD] fp32
    const int tid  = threadIdx.x;
    const int lane = tid & 31;
    const int w    = tid >> 5;
    const int gid  = lane >> 2;
    const int t4   = lane & 3;

    for (int idx = tid; idx < 128 * 128; idx += 512) {
        int k = idx >> 7, n = idx & 127;
        WTs[n * PAD + k] = f2tf(Ws[idx]);
        WTt[n * PAD + k] = f2tf(Wt[idx]);
    }
    __syncthreads();

    const int rb = (w >> 2) * 16;
    const int cb = (w & 3) * 32;

    for (int tile = blockIdx.x; tile < numTiles; tile += gridDim.x) {
        const int base = tile * 64;

        // normalize ent rows -> hsA (warp per 4 rows)
        #pragma unroll
        for (int rr = 0; rr < 4; rr++) {
            int row = w * 4 + rr, node = base + row;
            uint4 o = make_uint4(0u, 0u, 0u, 0u);
            if (node < N) {
                float4 v = *(const float4*)(ent + (size_t)node * 128 + lane * 4);
                float ss = v.x * v.x + v.y * v.y + v.z * v.z + v.w * v.w;
                #pragma unroll
                for (int off = 16; off > 0; off >>= 1)
                    ss += __shfl_xor_sync(0xffffffffu, ss, off);
                float rn = 1.0f / fmaxf(sqrtf(ss), 1e-12f);
                o = make_uint4(f2tf(v.x * rn), f2tf(v.y * rn),
                               f2tf(v.z * rn), f2tf(v.w * rn));
            }
            *(uint4*)(hsA + row * PAD + lane * 4) = o;
        }
        // agg tile -> hs2 (coalesced)
        for (int i = tid; i < 64 * 32; i += 512) {
            int row = i >> 5, kq = i & 31, node = base + row;
            float4 v = make_float4(0.f, 0.f, 0.f, 0.f);
            if (node < N) v = *(const float4*)(x + (size_t)node * 128 + kq * 4);
            *(float4*)(hs2 + row * PAD + kq * 4) = v;
        }
        __syncthreads();

        // MMA1: h @ Ws^T
        float acc[4][4];
        #pragma unroll
        for (int nt = 0; nt < 4; nt++)
            #pragma unroll
            for (int i = 0; i < 4; i++) acc[nt][i] = 0.f;

        #pragma unroll
        for (int s = 0; s < 16; s++) {
            const int kb = s * 8;
            u32 a0 = hsA[(rb + gid) * PAD + kb + t4];
            u32 a1 = hsA[(rb + 8 + gid) * PAD + kb + t4];
            u32 a2 = hsA[(rb + gid) * PAD + kb + t4 + 4];
            u32 a3 = hsA[(rb + 8 + gid) * PAD + kb + t4 + 4];
            #pragma unroll
            for (int nt = 0; nt < 4; nt++) {
                int c0 = cb + nt * 8 + gid;
                u32 b0 = WTs[c0 * PAD + kb + t4];
                u32 b1 = WTs[c0 * PAD + kb + t4 + 4];
                mma8(acc[nt], a0, a1, a2, a3, b0, b1);
            }
        }

        // epilogue1: h_cur = rrelu(acc + agg); owner-writes into hs2
        #pragma unroll
        for (int nt = 0; nt < 4; nt++) {
            int rl = rb + gid;
            int c  = cb + nt * 8 + 2 * t4;
            #pragma unroll
            for (int half = 0; half < 2; half++) {
                int row = rl + half * 8;
                float v0 = acc[nt][half * 2 + 0] + hs2[row * PAD + c];
                float v1 = acc[nt][half * 2 + 1] + hs2[row * PAD + c + 1];
                v0 = v0 >= 0.f ? v0 : RRELU_SLOPE * v0;
                v1 = v1 >= 0.f ? v1 : RRELU_SLOPE * v1;
                hs2[row * PAD + c]     = v0;
                hs2[row * PAD + c + 1] = v1;
            }
        }
        __syncthreads();

        // MMA2: h_cur @ Wt^T
        #pragma unroll
        for (int nt = 0; nt < 4; nt++)
            #pragma unroll
            for (int i = 0; i < 4; i++) acc[nt][i] = 0.f;

        #pragma unroll
        for (int s = 0; s < 16; s++) {
            const int kb = s * 8;
            u32 a0 = f2tf(hs2[(rb + gid) * PAD + kb + t4]);
            u32 a1 = f2tf(hs2[(rb + 8 + gid) * PAD + kb + t4]);
            u32 a2 = f2tf(hs2[(rb + gid) * PAD + kb + t4 + 4]);
            u32 a3 = f2tf(hs2[(rb + 8 + gid) * PAD + kb + t4 + 4]);
            #pragma unroll
            for (int nt = 0; nt < 4; nt++) {
                int c0 = cb + nt * 8 + gid;
                u32 b0 = WTt[c0 * PAD + kb + t4];
                u32 b1 = WTt[c0 * PAD + kb + t4 + 4];
                mma8(acc[nt], a0, a1, a2, a3, b0, b1);
            }
        }

        // epilogue2: sigmoid gate + blend with his -> x
        #pragma unroll
        for (int nt = 0; nt < 4; nt++) {
            int rl = rb + gid;
            int c  = cb + nt * 8 + 2 * t4;
            float2 bv = *(const float2*)(bias + c);
            #pragma unroll
            for (int half = 0; half < 2; half++) {
                int row  = rl + half * 8;
                int node = base + row;
                if (node >= N) continue;
                float l0 = acc[nt][half * 2 + 0] + bv.x;
                float l1 = acc[nt][half * 2 + 1] + bv.y;
                float s0 = 1.0f / (1.0f + __expf(-l0));
                float s1 = 1.0f / (1.0f + __expf(-l1));
                float2 hv = *(const float2*)(hs2 + row * PAD + c);
                float2 hh = *(const float2*)(his + (size_t)node * 128 + c);
                float2 o = make_float2(s0 * hv.x + (1.f - s0) * hh.x,
                                       s1 * hv.y + (1.f - s1) * hh.y);
                *(float2*)(x + (size_t)node * 128 + c) = o;
            }
        }
        __syncthreads();
    }
}

// ---------------------------------------------------------------------------
extern "C" void kernel_launch(void* const* d_in, const int* in_sizes, int n_in,
                              void* d_out, int out_size)
{
    const float* ent   = (const float*)d_in[0];
    const float* rel   = (const float*)d_in[1];
    const float* his   = (const float*)d_in[2];
    const float* Wn    = (const float*)d_in[3];
    const float* Ws    = (const float*)d_in[4];
    const float* Wt    = (const float*)d_in[5];
    const float* bias  = (const float*)d_in[6];
    const float* enorm = (const float*)d_in[7];
    const int*   src   = (const int*)d_in[8];
    const int*   dst   = (const int*)d_in[9];
    const int*   et    = (const int*)d_in[10];

    int N = in_sizes[0] / DHID;
    int R = in_sizes[1] / DHID;
    int E = in_sizes[7];
    float* out = (float*)d_out;

    int* cnt;
    cudaGetSymbolAddress((void**)&cnt, g_cnt);

    int dev = 0, sms = 148;
    cudaGetDevice(&dev);
    cudaDeviceGetAttribute(&sms, cudaDevAttrMultiProcessorCount, dev);

    const int numTiles  = (N + 63) / 64;
    const int numTilesG = (N + R + 63) / 64;
    const int nb        = (N + 1023) / 1024;
    const int smG = (128 * PAD + 64 * PAD) * sizeof(float);        // ~101.4 KB
    const int smF = (2 * 128 * PAD + 2 * 64 * PAD) * sizeof(float); // ~202.8 KB
    cudaFuncSetAttribute(k_gemm16, cudaFuncAttributeMaxDynamicSharedMemorySize, smG);
    cudaFuncSetAttribute(k_finalX, cudaFuncAttributeMaxDynamicSharedMemorySize, smF);
    cudaFuncSetAttribute(k_agg2, cudaFuncAttributePreferredSharedMemoryCarveout,
                         cudaSharedmemCarveoutMaxL1);

    static cudaStream_t s_side = nullptr;
    static cudaEvent_t  ev_fork = nullptr, ev_join = nullptr;
    if (s_side == nullptr) {
        cudaStreamCreateWithFlags(&s_side, cudaStreamNonBlocking);
        cudaEventCreateWithFlags(&ev_fork, cudaEventDisableTiming);
        cudaEventCreateWithFlags(&ev_join, cudaEventDisableTiming);
    }

    // ---- fork: edge counting-sort chain on side stream -------------------
    cudaEventRecord(ev_fork, 0);
    cudaStreamWaitEvent(s_side, ev_fork, 0);
    k_zero<<<nb, 1024, 0, s_side>>>(cnt, N);
    k_hist<<<(E + 255) / 256, 256, 0, s_side>>>(dst, E);
    k_scan1<<<nb, 1024, 0, s_side>>>(N);
    k_scan2<<<1, 256, 0, s_side>>>(nb);
    k_scan3<<<nb, 1024, 0, s_side>>>(N);
    k_scatter<<<(E + 255) / 256, 256, 0, s_side>>>(src, dst, et, enorm, E);
    cudaEventRecord(ev_join, s_side);

    // ---- main stream: message GEMM (overlapped with sort) ----------------
    k_gemm16<<<2 * sms, 512, smG>>>(ent, rel, Wn, N, R, numTilesG);

    // ---- join, aggregate (acc=0, writes message sums), then fused final --
    cudaStreamWaitEvent(0, ev_join, 0);
    k_agg2<<<(N + 15) / 16, 256>>>(out, N);
    k_finalX<<<sms, 512, smF>>>(out, ent, Ws, Wt, bias, his, N, numTiles);
}

// round 14
// speedup vs baseline: 1.1324x; 1.1324x over previous
#include <cuda_runtime.h>
#include <cuda_fp16.h>
#include <cstdint>
#include <math.h>

#define DHID 128
#define MAX_ENTS 100000
#define MAX_RELS 1000
#define MAX_EDGES 2000000
#define RRELU_SLOPE 0.22916666666666666f
#define PAD 132

typedef uint32_t u32;

__device__ __half2 g_hWh[MAX_ENTS * 64];         // h@Wn fp16
__device__ __half2 g_relWh[MAX_RELS * 64];       // rel@Wn fp16
__device__ float   g_aggbuf[MAX_ENTS * DHID];    // message sums
__device__ int     g_cnt[MAX_ENTS];              // per-dst edge counts
__device__ int     g_off[MAX_ENTS];              // bucket start offsets
__device__ int     g_cur[MAX_ENTS];              // scatter cursors
__device__ int     g_bsum[256];                  // scan partials
__device__ uint2   g_rec[MAX_EDGES];             // (src | et<<17, norm_bits)

__device__ __forceinline__ u32 f2tf(float x) {
    u32 r; asm("cvt.rna.tf32.f32 %0, %1;" : "=r"(r) : "f"(x)); return r;
}
__device__ __forceinline__ void mma8(float* c, u32 a0, u32 a1, u32 a2, u32 a3,
                                     u32 b0, u32 b1) {
    asm volatile(
        "mma.sync.aligned.m16n8k8.row.col.f32.tf32.tf32.f32 "
        "{%0,%1,%2,%3}, {%4,%5,%6,%7}, {%8,%9}, {%0,%1,%2,%3};"
        : "+f"(c[0]), "+f"(c[1]), "+f"(c[2]), "+f"(c[3])
        : "r"(a0), "r"(a1), "r"(a2), "r"(a3), "r"(b0), "r"(b1));
}
__device__ __forceinline__ void add8(float4& acc0, float4& acc1,
                                     uint4 a, uint4 b, float n) {
    float2 p, q;
    p = __half22float2(*(__half2*)&a.x); q = __half22float2(*(__half2*)&b.x);
    acc0.x += (p.x + q.x) * n; acc0.y += (p.y + q.y) * n;
    p = __half22float2(*(__half2*)&a.y); q = __half22float2(*(__half2*)&b.y);
    acc0.z += (p.x + q.x) * n; acc0.w += (p.y + q.y) * n;
    p = __half22float2(*(__half2*)&a.z); q = __half22float2(*(__half2*)&b.z);
    acc1.x += (p.x + q.x) * n; acc1.y += (p.y + q.y) * n;
    p = __half22float2(*(__half2*)&a.w); q = __half22float2(*(__half2*)&b.w);
    acc1.z += (p.x + q.x) * n; acc1.w += (p.y + q.y) * n;
}

// ---------------------------------------------------------------------------
// Edge counting sort by dst (side stream, overlapped with gemm16)
// ---------------------------------------------------------------------------
extern "C" __global__ void k_zero(int* __restrict__ p, int n) {
    int i = blockIdx.x * 1024 + threadIdx.x;
    if (i < n) p[i] = 0;
}

extern "C" __global__ void __launch_bounds__(256)
k_hist(const int* __restrict__ dst, int E)
{
    int e = blockIdx.x * 256 + threadIdx.x;
    if (e < E) atomicAdd(&g_cnt[dst[e]], 1);
}

extern "C" __global__ void __launch_bounds__(1024)
k_scan1(int N)
{
    __shared__ int smi[1024];
    int i = blockIdx.x * 1024 + threadIdx.x;
    int v = (i < N) ? g_cnt[i] : 0;
    smi[threadIdx.x] = v;
    __syncthreads();
    for (int off = 512; off > 0; off >>= 1) {
        if (threadIdx.x < off) smi[threadIdx.x] += smi[threadIdx.x + off];
        __syncthreads();
    }
    if (threadIdx.x == 0) g_bsum[blockIdx.x] = smi[0];
}

extern "C" __global__ void __launch_bounds__(256)
k_scan2(int nb)
{
    __shared__ int s[256];
    int t = threadIdx.x;
    int v = (t < nb) ? g_bsum[t] : 0;
    s[t] = v;
    __syncthreads();
    #pragma unroll
    for (int off = 1; off < 256; off <<= 1) {
        int x = (t >= off) ? s[t - off] : 0;
        __syncthreads();
        s[t] += x;
        __syncthreads();
    }
    if (t < nb) g_bsum[t] = s[t] - v;   // exclusive
}

extern "C" __global__ void __launch_bounds__(1024)
k_scan3(int N)
{
    __shared__ int smi[1024];
    int i = blockIdx.x * 1024 + threadIdx.x;
    int v = (i < N) ? g_cnt[i] : 0;
    smi[threadIdx.x] = v;
    __syncthreads();
    #pragma unroll
    for (int off = 1; off < 1024; off <<= 1) {
        int x = (threadIdx.x >= off) ? smi[threadIdx.x - off] : 0;
        __syncthreads();
        smi[threadIdx.x] += x;
        __syncthreads();
    }
    if (i < N) {
        int ex = smi[threadIdx.x] - v + g_bsum[blockIdx.x];
        g_off[i] = ex;
        g_cur[i] = ex;
    }
}

extern "C" __global__ void __launch_bounds__(256)
k_scatter(const int* __restrict__ src, const int* __restrict__ dst,
          const int* __restrict__ et, const float* __restrict__ enorm, int E)
{
    int e = blockIdx.x * 256 + threadIdx.x;
    if (e >= E) return;
    int d   = dst[e];
    int pos = atomicAdd(&g_cur[d], 1);
    g_rec[pos] = make_uint2((u32)src[e] | ((u32)et[e] << 17),
                            __float_as_uint(enorm[e]));
}

// ---------------------------------------------------------------------------
// k_gemm16: fp16 out = normalize(ent) @ Wn rows [0,N); rel rows [N,N+R).
// Persistent, 2 CTA/SM. smem: WT[128][PAD] | hs[64][PAD] tf32.
// ---------------------------------------------------------------------------
extern "C" __global__ void __launch_bounds__(512, 2)
k_gemm16(const float* __restrict__ ent, const float* __restrict__ rel,
         const float* __restrict__ W, int N, int R, int numTiles)
{
    extern __shared__ u32 smu[];
    u32* WT = smu;               // [n][k] tf32
    u32* hs = smu + 128 * PAD;   // [row][k] tf32
    const int tid  = threadIdx.x;
    const int lane = tid & 31;
    const int w    = tid >> 5;
    const int gid  = lane >> 2;
    const int t4   = lane & 3;

    for (int idx = tid; idx < 128 * 128; idx += 512) {
        int k = idx >> 7, n = idx & 127;
        WT[n * PAD + k] = f2tf(W[idx]);
    }
    __syncthreads();

    const int rb = (w >> 2) * 16;
    const int cb = (w & 3) * 32;

    for (int tile = blockIdx.x; tile < numTiles; tile += gridDim.x) {
        const int base = tile * 64;

        #pragma unroll
        for (int rr = 0; rr < 4; rr++) {
            int row = w * 4 + rr, node = base + row;
            uint4 o = make_uint4(0u, 0u, 0u, 0u);
            if (node < N) {
                float4 v = *(const float4*)(ent + (size_t)node * 128 + lane * 4);
                float ss = v.x * v.x + v.y * v.y + v.z * v.z + v.w * v.w;
                #pragma unroll
                for (int off = 16; off > 0; off >>= 1)
                    ss += __shfl_xor_sync(0xffffffffu, ss, off);
                float rn = 1.0f / fmaxf(sqrtf(ss), 1e-12f);
                o = make_uint4(f2tf(v.x * rn), f2tf(v.y * rn),
                               f2tf(v.z * rn), f2tf(v.w * rn));
            } else if (node < N + R) {
                float4 v = *(const float4*)(rel + (size_t)(node - N) * 128 + lane * 4);
                o = make_uint4(f2tf(v.x), f2tf(v.y), f2tf(v.z), f2tf(v.w));
            }
            *(uint4*)(hs + row * PAD + lane * 4) = o;
        }
        __syncthreads();

        float acc[4][4];
        #pragma unroll
        for (int nt = 0; nt < 4; nt++)
            #pragma unroll
            for (int i = 0; i < 4; i++) acc[nt][i] = 0.f;

        #pragma unroll
        for (int s = 0; s < 16; s++) {
            const int kb = s * 8;
            u32 a0 = hs[(rb + gid) * PAD + kb + t4];
            u32 a1 = hs[(rb + 8 + gid) * PAD + kb + t4];
            u32 a2 = hs[(rb + gid) * PAD + kb + t4 + 4];
            u32 a3 = hs[(rb + 8 + gid) * PAD + kb + t4 + 4];
            #pragma unroll
            for (int nt = 0; nt < 4; nt++) {
                int c0 = cb + nt * 8 + gid;
                u32 b0 = WT[c0 * PAD + kb + t4];
                u32 b1 = WT[c0 * PAD + kb + t4 + 4];
                mma8(acc[nt], a0, a1, a2, a3, b0, b1);
            }
        }

        #pragma unroll
        for (int nt = 0; nt < 4; nt++) {
            int rl = rb + gid;
            int c  = cb + nt * 8 + 2 * t4;
            #pragma unroll
            for (int half = 0; half < 2; half++) {
                int node = base + rl + half * 8;
                __half2 p = __floats2half2_rn(acc[nt][half * 2], acc[nt][half * 2 + 1]);
                if (node < N)          g_hWh[(size_t)node * 64 + (c >> 1)] = p;
                else if (node < N + R) g_relWh[(size_t)(node - N) * 64 + (c >> 1)] = p;
            }
        }
        __syncthreads();
    }
}

// ---------------------------------------------------------------------------
// k_gemm32: x = normalize(ent) @ Ws. Persistent, 2 CTA/SM.
// Runs on a second side stream, concurrent with k_agg2.
// ---------------------------------------------------------------------------
extern "C" __global__ void __launch_bounds__(512, 2)
k_gemm32(const float* __restrict__ ent, const float* __restrict__ W,
         float* __restrict__ out, int N, int numTiles)
{
    extern __shared__ u32 smu[];
    u32* WT = smu;
    u32* hs = smu + 128 * PAD;
    const int tid  = threadIdx.x;
    const int lane = tid & 31;
    const int w    = tid >> 5;
    const int gid  = lane >> 2;
    const int t4   = lane & 3;

    for (int idx = tid; idx < 128 * 128; idx += 512) {
        int k = idx >> 7, n = idx & 127;
        WT[n * PAD + k] = f2tf(W[idx]);
    }
    __syncthreads();

    const int rb = (w >> 2) * 16;
    const int cb = (w & 3) * 32;

    for (int tile = blockIdx.x; tile < numTiles; tile += gridDim.x) {
        const int base = tile * 64;

        #pragma unroll
        for (int rr = 0; rr < 4; rr++) {
            int row = w * 4 + rr, node = base + row;
            uint4 o = make_uint4(0u, 0u, 0u, 0u);
            if (node < N) {
                float4 v = *(const float4*)(ent + (size_t)node * 128 + lane * 4);
                float ss = v.x * v.x + v.y * v.y + v.z * v.z + v.w * v.w;
                #pragma unroll
                for (int off = 16; off > 0; off >>= 1)
                    ss += __shfl_xor_sync(0xffffffffu, ss, off);
                float rn = 1.0f / fmaxf(sqrtf(ss), 1e-12f);
                o = make_uint4(f2tf(v.x * rn), f2tf(v.y * rn),
                               f2tf(v.z * rn), f2tf(v.w * rn));
            }
            *(uint4*)(hs + row * PAD + lane * 4) = o;
        }
        __syncthreads();

        float acc[4][4];
        #pragma unroll
        for (int nt = 0; nt < 4; nt++)
            #pragma unroll
            for (int i = 0; i < 4; i++) acc[nt][i] = 0.f;

        #pragma unroll
        for (int s = 0; s < 16; s++) {
            const int kb = s * 8;
            u32 a0 = hs[(rb + gid) * PAD + kb + t4];
            u32 a1 = hs[(rb + 8 + gid) * PAD + kb + t4];
            u32 a2 = hs[(rb + gid) * PAD + kb + t4 + 4];
            u32 a3 = hs[(rb + 8 + gid) * PAD + kb + t4 + 4];
            #pragma unroll
            for (int nt = 0; nt < 4; nt++) {
                int c0 = cb + nt * 8 + gid;
                u32 b0 = WT[c0 * PAD + kb + t4];
                u32 b1 = WT[c0 * PAD + kb + t4 + 4];
                mma8(acc[nt], a0, a1, a2, a3, b0, b1);
            }
        }

        #pragma unroll
        for (int nt = 0; nt < 4; nt++) {
            int rl = rb + gid;
            int c  = cb + nt * 8 + 2 * t4;
            int n0 = base + rl, n1 = base + rl + 8;
            if (n0 < N) *(float2*)(out + (size_t)n0 * 128 + c) =
                make_float2(acc[nt][0], acc[nt][1]);
            if (n1 < N) *(float2*)(out + (size_t)n1 * 128 + c) =
                make_float2(acc[nt][2], acc[nt][3]);
        }
        __syncthreads();
    }
}

// ---------------------------------------------------------------------------
// k_agg2: HALF-WARP per dst (16 lanes x uint4 = 256B row), no smem.
// acc = 0 + sum (hW[src]+relW[et])*norm; writes message sums into aggbuf.
// Concurrent with k_gemm32 (latency-bound vs tensor-bound — complementary).
// ---------------------------------------------------------------------------
extern "C" __global__ void __launch_bounds__(256)
k_agg2(float* __restrict__ aggb, int N)
{
    int d = blockIdx.x * 16 + (threadIdx.x >> 4);
    if (d >= N) return;
    int l = threadIdx.x & 15;

    const uint4* hW4  = (const uint4*)g_hWh;     // 16 uint4 per row
    const uint4* rlW4 = (const uint4*)g_relWh;

    float4 acc0 = make_float4(0.f, 0.f, 0.f, 0.f);
    float4 acc1 = make_float4(0.f, 0.f, 0.f, 0.f);
    const int s0  = g_off[d];
    const int cnt = g_cnt[d];

    int i = 0;
    for (; i + 4 <= cnt; i += 4) {
        uint2 r0 = __ldg(&g_rec[s0 + i]);
        uint2 r1 = __ldg(&g_rec[s0 + i + 1]);
        uint2 r2 = __ldg(&g_rec[s0 + i + 2]);
        uint2 r3 = __ldg(&g_rec[s0 + i + 3]);
        uint4 a0 = __ldg(&hW4[(size_t)(r0.x & 0x1FFFF) * 16 + l]);
        uint4 a1 = __ldg(&hW4[(size_t)(r1.x & 0x1FFFF) * 16 + l]);
        uint4 a2 = __ldg(&hW4[(size_t)(r2.x & 0x1FFFF) * 16 + l]);
        uint4 a3 = __ldg(&hW4[(size_t)(r3.x & 0x1FFFF) * 16 + l]);
        uint4 b0 = __ldg(&rlW4[(size_t)(r0.x >> 17) * 16 + l]);
        uint4 b1 = __ldg(&rlW4[(size_t)(r1.x >> 17) * 16 + l]);
        uint4 b2 = __ldg(&rlW4[(size_t)(r2.x >> 17) * 16 + l]);
        uint4 b3 = __ldg(&rlW4[(size_t)(r3.x >> 17) * 16 + l]);
        add8(acc0, acc1, a0, b0, __uint_as_float(r0.y));
        add8(acc0, acc1, a1, b1, __uint_as_float(r1.y));
        add8(acc0, acc1, a2, b2, __uint_as_float(r2.y));
        add8(acc0, acc1, a3, b3, __uint_as_float(r3.y));
    }
    for (; i < cnt; i++) {
        uint2 r = __ldg(&g_rec[s0 + i]);
        uint4 a = __ldg(&hW4[(size_t)(r.x & 0x1FFFF) * 16 + l]);
        uint4 b = __ldg(&rlW4[(size_t)(r.x >> 17) * 16 + l]);
        add8(acc0, acc1, a, b, __uint_as_float(r.y));
    }

    *(float4*)(aggb + (size_t)d * 128 + l * 8)     = acc0;
    *(float4*)(aggb + (size_t)d * 128 + l * 8 + 4) = acc1;
}

// ---------------------------------------------------------------------------
// k_final: h_cur = rrelu(x + aggbuf)  (x holds h@Ws);
// gate = sigmoid(h_cur@Wt + b); x = gate*h_cur + (1-gate)*his.
// Persistent, 2 CTA/SM, 64-row tiles.
// ---------------------------------------------------------------------------
extern "C" __global__ void __launch_bounds__(512, 2)
k_final(float* __restrict__ x,
        const float* __restrict__ aggb,
        const float* __restrict__ Wt,
        const float* __restrict__ bias,
        const float* __restrict__ his,
        int N, int numTiles)
{
    extern __shared__ float sm[];
    u32*   WT = (u32*)sm;          // [n][k] tf32
    float* hs = sm + 128 * PAD;    // [row][k] fp32 h_cur
    const int tid  = threadIdx.x;
    const int lane = tid & 31;
    const int w    = tid >> 5;
    const int gid  = lane >> 2;
    const int t4   = lane & 3;

    for (int idx = tid; idx < 128 * 128; idx += 512) {
        int k = idx >> 7, n = idx & 127;
        WT[n * PAD + k] = f2tf(Wt[idx]);
    }
    __syncthreads();

    const int rb = (w >> 2) * 16;
    const int cb = (w & 3) * 32;

    for (int tile = blockIdx.x; tile < numTiles; tile += gridDim.x) {
        const int base = tile * 64;

        for (int i = tid; i < 64 * 32; i += 512) {
            int row = i >> 5, kq = i & 31, node = base + row;
            float4 v = make_float4(0.f, 0.f, 0.f, 0.f);
            if (node < N) {
                float4 a = *(const float4*)(x    + (size_t)node * 128 + kq * 4);
                float4 b = *(const float4*)(aggb + (size_t)node * 128 + kq * 4);
                v = make_float4(a.x + b.x, a.y + b.y, a.z + b.z, a.w + b.w);
                v.x = v.x >= 0.f ? v.x : RRELU_SLOPE * v.x;
                v.y = v.y >= 0.f ? v.y : RRELU_SLOPE * v.y;
                v.z = v.z >= 0.f ? v.z : RRELU_SLOPE * v.z;
                v.w = v.w >= 0.f ? v.w : RRELU_SLOPE * v.w;
            }
            *(float4*)(hs + row * PAD + kq * 4) = v;
        }
        __syncthreads();

        float acc[4][4];
        #pragma unroll
        for (int nt = 0; nt < 4; nt++)
            #pragma unroll
            for (int i = 0; i < 4; i++) acc[nt][i] = 0.f;

        #pragma unroll
        for (int s = 0; s < 16; s++) {
            const int kb = s * 8;
            u32 a0 = f2tf(hs[(rb + gid) * PAD + kb + t4]);
            u32 a1 = f2tf(hs[(rb + 8 + gid) * PAD + kb + t4]);
            u32 a2 = f2tf(hs[(rb + gid) * PAD + kb + t4 + 4]);
            u32 a3 = f2tf(hs[(rb + 8 + gid) * PAD + kb + t4 + 4]);
            #pragma unroll
            for (int nt = 0; nt < 4; nt++) {
                int c0 = cb + nt * 8 + gid;
                u32 b0 = WT[c0 * PAD + kb + t4];
                u32 b1 = WT[c0 * PAD + kb + t4 + 4];
                mma8(acc[nt], a0, a1, a2, a3, b0, b1);
            }
        }

        #pragma unroll
        for (int nt = 0; nt < 4; nt++) {
            int rl = rb + gid;
            int c  = cb + nt * 8 + 2 * t4;
            float2 bv = *(const float2*)(bias + c);
            #pragma unroll
            for (int half = 0; half < 2; half++) {
                int row  = rl + half * 8;
                int node = base + row;
                if (node >= N) continue;
                float l0 = acc[nt][half * 2 + 0] + bv.x;
                float l1 = acc[nt][half * 2 + 1] + bv.y;
                float s0 = 1.0f / (1.0f + __expf(-l0));
                float s1 = 1.0f / (1.0f + __expf(-l1));
                float2 hv = *(const float2*)(hs + row * PAD + c);
                float2 hh = *(const float2*)(his + (size_t)node * 128 + c);
                float2 o = make_float2(s0 * hv.x + (1.f - s0) * hh.x,
                                       s1 * hv.y + (1.f - s1) * hh.y);
                *(float2*)(x + (size_t)node * 128 + c) = o;
            }
        }
        __syncthreads();
    }
}

// ---------------------------------------------------------------------------
extern "C" void kernel_launch(void* const* d_in, const int* in_sizes, int n_in,
                              void* d_out, int out_size)
{
    const float* ent   = (const float*)d_in[0];
    const float* rel   = (const float*)d_in[1];
    const float* his   = (const float*)d_in[2];
    const float* Wn    = (const float*)d_in[3];
    const float* Ws    = (const float*)d_in[4];
    const float* Wt    = (const float*)d_in[5];
    const float* bias  = (const float*)d_in[6];
    const float* enorm = (const float*)d_in[7];
    const int*   src   = (const int*)d_in[8];
    const int*   dst   = (const int*)d_in[9];
    const int*   et    = (const int*)d_in[10];

    int N = in_sizes[0] / DHID;
    int R = in_sizes[1] / DHID;
    int E = in_sizes[7];
    float* out = (float*)d_out;

    int* cnt; float* aggb;
    cudaGetSymbolAddress((void**)&cnt,  g_cnt);
    cudaGetSymbolAddress((void**)&aggb, g_aggbuf);

    int dev = 0, sms = 148;
    cudaGetDevice(&dev);
    cudaDeviceGetAttribute(&sms, cudaDevAttrMultiProcessorCount, dev);

    const int numTiles  = (N + 63) / 64;
    const int numTilesG = (N + R + 63) / 64;
    const int nb        = (N + 1023) / 1024;
    const int smG = (128 * PAD + 64 * PAD) * sizeof(float);   // ~101.4 KB
    cudaFuncSetAttribute(k_gemm16, cudaFuncAttributeMaxDynamicSharedMemorySize, smG);
    cudaFuncSetAttribute(k_gemm32, cudaFuncAttributeMaxDynamicSharedMemorySize, smG);
    cudaFuncSetAttribute(k_final,  cudaFuncAttributeMaxDynamicSharedMemorySize, smG);
    cudaFuncSetAttribute(k_agg2, cudaFuncAttributePreferredSharedMemoryCarveout,
                         cudaSharedmemCarveoutMaxL1);

    static cudaStream_t s_side = nullptr, s_g32 = nullptr;
    static cudaEvent_t  ev_fork = nullptr, ev_join = nullptr,
                        ev_g16 = nullptr, ev_g32 = nullptr;
    if (s_side == nullptr) {
        cudaStreamCreateWithFlags(&s_side, cudaStreamNonBlocking);
        cudaStreamCreateWithFlags(&s_g32,  cudaStreamNonBlocking);
        cudaEventCreateWithFlags(&ev_fork, cudaEventDisableTiming);
        cudaEventCreateWithFlags(&ev_join, cudaEventDisableTiming);
        cudaEventCreateWithFlags(&ev_g16,  cudaEventDisableTiming);
        cudaEventCreateWithFlags(&ev_g32,  cudaEventDisableTiming);
    }

    // ---- fork: edge counting-sort chain on side stream -------------------
    cudaEventRecord(ev_fork, 0);
    cudaStreamWaitEvent(s_side, ev_fork, 0);
    k_zero<<<nb, 1024, 0, s_side>>>(cnt, N);
    k_hist<<<(E + 255) / 256, 256, 0, s_side>>>(dst, E);
    k_scan1<<<nb, 1024, 0, s_side>>>(N);
    k_scan2<<<1, 256, 0, s_side>>>(nb);
    k_scan3<<<nb, 1024, 0, s_side>>>(N);
    k_scatter<<<(E + 255) / 256, 256, 0, s_side>>>(src, dst, et, enorm, E);
    cudaEventRecord(ev_join, s_side);

    // ---- main stream: message GEMM (overlapped with sort) ----------------
    k_gemm16<<<2 * sms, 512, smG>>>(ent, rel, Wn, N, R, numTilesG);
    cudaEventRecord(ev_g16, 0);

    // ---- second side stream: self-loop GEMM, concurrent with agg ---------
    cudaStreamWaitEvent(s_g32, ev_g16, 0);
    k_gemm32<<<2 * sms, 512, smG, s_g32>>>(ent, Ws, out, N, numTiles);
    cudaEventRecord(ev_g32, s_g32);

    // ---- main: aggregate (needs gemm16 + sort), then gate ----------------
    cudaStreamWaitEvent(0, ev_join, 0);
    k_agg2<<<(N + 15) / 16, 256>>>(aggb, N);
    cudaStreamWaitEvent(0, ev_g32, 0);
    k_final<<<2 * sms, 512, smG>>>(out, aggb, Wt, bias, his, N, numTiles);
}